// round 3
// baseline (speedup 1.0000x reference)
#include <cuda_runtime.h>
#include <math.h>

#define BB 64
#define TT 128
#define DD 512
#define NBD (BB*DD)        /* 32768 */
#define BTD (BB*TT*DD)     /* 4194304 */

// ---------------- device state ----------------
__device__ float g_Q[TT*NBD];
__device__ float g_K[TT*NBD];
__device__ float g_V[TT*NBD];
__device__ float g_th[TT], g_et[TT], g_al[TT];
__device__ float g_W1[DD*DD], g_M1w[DD*DD], g_b1[DD], g_M1b[DD];
__device__ float g_W2[DD*DD], g_M2w[DD*DD], g_b2[DD], g_M2b[DD];
__device__ float g_h[2*NBD];      // raw pre-activations: rows 0-63 q-path, 64-127 k-path
__device__ float g_diff[NBD];     // out - v (UNSCALED)
__device__ float g_dpre[NBD];     // masked diff@W2 (UNSCALED)
__device__ float g_gW1[DD*DD], g_gW2[DD*DD];
__device__ float g_loss[TT];      // sum of squared diffs (not yet /N)

// ---------------- init: copy weights, zero momentum + loss ----------------
__global__ void k_init(const float* __restrict__ W1, const float* __restrict__ b1,
                       const float* __restrict__ W2, const float* __restrict__ b2) {
    int i = blockIdx.x * 256 + threadIdx.x;
    if (i < DD*DD) { g_W1[i] = W1[i]; g_M1w[i] = 0.f; g_W2[i] = W2[i]; g_M2w[i] = 0.f; }
    if (i < DD)    { g_b1[i] = b1[i]; g_M1b[i] = 0.f; g_b2[i] = b2[i]; g_M2b[i] = 0.f; }
    if (i < TT)    g_loss[i] = 0.f;
}

// ---------------- gates: mean_b sigmoid(x_t . w + b) for theta/eta/alpha ----------------
__global__ void k_gates(const float* __restrict__ x,
                        const float* __restrict__ thw, const float* __restrict__ thb,
                        const float* __restrict__ etw, const float* __restrict__ etb,
                        const float* __restrict__ alw, const float* __restrict__ alb) {
    int t = blockIdx.x, tid = threadIdx.x, lane = tid & 31, warp = tid >> 5;
    __shared__ float red[8];
    for (int g = 0; g < 3; g++) {
        const float* w = (g == 0) ? thw : ((g == 1) ? etw : alw);
        float b0 = (g == 0) ? thb[0] : ((g == 1) ? etb[0] : alb[0]);
        float acc = 0.f;
        for (int bi = warp; bi < BB; bi += 8) {
            const float* xr = x + ((size_t)bi * TT + t) * DD;
            float s = 0.f;
            for (int k = lane; k < DD; k += 32) s += xr[k] * w[k];
            #pragma unroll
            for (int o = 16; o; o >>= 1) s += __shfl_down_sync(0xffffffffu, s, o);
            if (lane == 0) acc += 1.f / (1.f + expf(-(s + b0)));
        }
        if (lane == 0) red[warp] = acc;
        __syncthreads();
        if (tid == 0) {
            float s = 0.f;
            #pragma unroll
            for (int i = 0; i < 8; i++) s += red[i];
            s *= (1.f / (float)BB);
            if (g == 0) g_th[t] = s; else if (g == 1) g_et[t] = s; else g_al[t] = s;
        }
        __syncthreads();
    }
}

// ---------------- QKV: g_{Q,K,V}[t][b][n] = sum_k x[b][t][k] * W[n][k] ----------------
__global__ __launch_bounds__(256) void k_qkv(const float* __restrict__ x,
                       const float* __restrict__ WQ, const float* __restrict__ WK,
                       const float* __restrict__ WV) {
    __shared__ float As[32][33], Bs[32][33];
    int n0 = blockIdx.x * 32, m0 = blockIdx.y * 32;
    const float* W = (blockIdx.z == 0) ? WQ : ((blockIdx.z == 1) ? WK : WV);
    float* O = (blockIdx.z == 0) ? g_Q : ((blockIdx.z == 1) ? g_K : g_V);
    int tx = threadIdx.x & 15, ty = threadIdx.x >> 4;
    float a00 = 0.f, a01 = 0.f, a10 = 0.f, a11 = 0.f;
    for (int k0 = 0; k0 < DD; k0 += 32) {
        for (int i = threadIdx.x; i < 1024; i += 256) {
            int r = i >> 5, c = i & 31;
            int m = m0 + r, t = m >> 6, b = m & 63;
            As[r][c] = x[((size_t)b * TT + t) * DD + k0 + c];
            Bs[r][c] = W[(size_t)(n0 + r) * DD + k0 + c];
        }
        __syncthreads();
        #pragma unroll
        for (int k = 0; k < 32; k++) {
            float x0 = As[ty*2][k], x1 = As[ty*2+1][k];
            float y0 = Bs[tx*2][k], y1 = Bs[tx*2+1][k];
            a00 += x0*y0; a01 += x0*y1; a10 += x1*y0; a11 += x1*y1;
        }
        __syncthreads();
    }
    int m = m0 + ty*2, n = n0 + tx*2;
    O[(size_t)m*DD + n] = a00;       O[(size_t)m*DD + n + 1] = a01;
    O[(size_t)(m+1)*DD + n] = a10;   O[(size_t)(m+1)*DD + n + 1] = a11;
}

// ---------------- per-step: h_raw = [q;k] @ W1^T + b1 ----------------
__global__ __launch_bounds__(256) void k_h(int t) {
    __shared__ float As[32][33], Bs[32][33];
    int n0 = blockIdx.x * 32, m0 = blockIdx.y * 32;
    int tx = threadIdx.x & 15, ty = threadIdx.x >> 4;
    const float* Qt = g_Q + (size_t)t * NBD;
    const float* Kt = g_K + (size_t)t * NBD;
    float a00 = 0.f, a01 = 0.f, a10 = 0.f, a11 = 0.f;
    for (int k0 = 0; k0 < DD; k0 += 32) {
        for (int i = threadIdx.x; i < 1024; i += 256) {
            int r = i >> 5, c = i & 31, m = m0 + r;
            As[r][c] = (m < 64) ? Qt[(size_t)m*DD + k0 + c] : Kt[(size_t)(m-64)*DD + k0 + c];
            Bs[r][c] = g_W1[(size_t)(n0 + r)*DD + k0 + c];
        }
        __syncthreads();
        #pragma unroll
        for (int k = 0; k < 32; k++) {
            float x0 = As[ty*2][k], x1 = As[ty*2+1][k];
            float y0 = Bs[tx*2][k], y1 = Bs[tx*2+1][k];
            a00 += x0*y0; a01 += x0*y1; a10 += x1*y0; a11 += x1*y1;
        }
        __syncthreads();
    }
    int m = m0 + ty*2, n = n0 + tx*2;
    float bb0 = g_b1[n], bb1 = g_b1[n+1];
    g_h[(size_t)m*DD + n] = a00 + bb0;       g_h[(size_t)m*DD + n + 1] = a01 + bb1;
    g_h[(size_t)(m+1)*DD + n] = a10 + bb0;   g_h[(size_t)(m+1)*DD + n + 1] = a11 + bb1;
}

// ---------------- per-step: out = relu(h_raw) @ W2^T + b2 -> mem output / diff / loss ----
__global__ __launch_bounds__(256) void k_out(int t, float* __restrict__ out, int dup) {
    __shared__ float As[32][33], Bs[32][33];
    __shared__ float red[8];
    int n0 = blockIdx.x * 32, m0 = blockIdx.y * 32;
    int tx = threadIdx.x & 15, ty = threadIdx.x >> 4;
    float a00 = 0.f, a01 = 0.f, a10 = 0.f, a11 = 0.f;
    for (int k0 = 0; k0 < DD; k0 += 32) {
        for (int i = threadIdx.x; i < 1024; i += 256) {
            int r = i >> 5, c = i & 31;
            As[r][c] = fmaxf(g_h[(size_t)(m0 + r)*DD + k0 + c], 0.f);
            Bs[r][c] = g_W2[(size_t)(n0 + r)*DD + k0 + c];
        }
        __syncthreads();
        #pragma unroll
        for (int k = 0; k < 32; k++) {
            float x0 = As[ty*2][k], x1 = As[ty*2+1][k];
            float y0 = Bs[tx*2][k], y1 = Bs[tx*2+1][k];
            a00 += x0*y0; a01 += x0*y1; a10 += x1*y0; a11 += x1*y1;
        }
        __syncthreads();
    }
    int m = m0 + ty*2, n = n0 + tx*2;
    float bb0 = g_b2[n], bb1 = g_b2[n+1];
    a00 += bb0; a01 += bb1; a10 += bb0; a11 += bb1;
    float lsum = 0.f;
    if (m < 64) {  // q-path: memory output
        size_t o0 = ((size_t)m*TT + t)*DD + n;
        size_t o1 = ((size_t)(m+1)*TT + t)*DD + n;
        out[o0] = a00; out[o0+1] = a01; out[o1] = a10; out[o1+1] = a11;
        if (dup) { out[BTD+o0] = a00; out[BTD+o0+1] = a01; out[BTD+o1] = a10; out[BTD+o1+1] = a11; }
    } else {       // k-path: diff + loss
        int b = m - 64;
        const float* vp0 = g_V + (size_t)t*NBD + (size_t)b*DD + n;
        const float* vp1 = vp0 + DD;
        float d0 = a00 - vp0[0], d1 = a01 - vp0[1];
        float d2 = a10 - vp1[0], d3 = a11 - vp1[1];
        float* dp = g_diff + (size_t)b*DD + n;
        dp[0] = d0; dp[1] = d1; dp[DD] = d2; dp[DD+1] = d3;
        lsum = d0*d0 + d1*d1 + d2*d2 + d3*d3;
    }
    if (m0 >= 64) {
        #pragma unroll
        for (int o = 16; o; o >>= 1) lsum += __shfl_down_sync(0xffffffffu, lsum, o);
        if ((threadIdx.x & 31) == 0) red[threadIdx.x >> 5] = lsum;
        __syncthreads();
        if (threadIdx.x == 0) {
            float s = 0.f;
            #pragma unroll
            for (int i = 0; i < 8; i++) s += red[i];
            atomicAdd(&g_loss[t], s);
        }
    }
}

// ---------------- per-step: dpre = mask(hpre_k>0) * (diff @ W2)  (UNSCALED) ----------------
__global__ __launch_bounds__(256) void k_dpre(int t) {
    __shared__ float As[32][33], Bs[32][33];
    int n0 = blockIdx.x * 32, m0 = blockIdx.y * 32;
    int tx = threadIdx.x & 15, ty = threadIdx.x >> 4;
    float a00 = 0.f, a01 = 0.f, a10 = 0.f, a11 = 0.f;
    for (int k0 = 0; k0 < DD; k0 += 32) {
        for (int i = threadIdx.x; i < 1024; i += 256) {
            int r = i >> 5, c = i & 31;
            As[r][c] = g_diff[(size_t)(m0 + r)*DD + k0 + c];
            Bs[r][c] = g_W2[(size_t)(k0 + r)*DD + n0 + c];
        }
        __syncthreads();
        #pragma unroll
        for (int k = 0; k < 32; k++) {
            float x0 = As[ty*2][k], x1 = As[ty*2+1][k];
            float y0 = Bs[k][tx*2], y1 = Bs[k][tx*2+1];
            a00 += x0*y0; a01 += x0*y1; a10 += x1*y0; a11 += x1*y1;
        }
        __syncthreads();
    }
    int m = m0 + ty*2, n = n0 + tx*2;
    const float* hp0 = g_h + (size_t)(64 + m)*DD + n;
    const float* hp1 = hp0 + DD;
    float* dp = g_dpre + (size_t)m*DD + n;
    dp[0]    = (hp0[0] > 0.f) ? a00 : 0.f;
    dp[1]    = (hp0[1] > 0.f) ? a01 : 0.f;
    dp[DD]   = (hp1[0] > 0.f) ? a10 : 0.f;
    dp[DD+1] = (hp1[1] > 0.f) ? a11 : 0.f;
}

// ---------------- per-step: gW1 = dpre^T @ k ; gW2 = diff^T @ relu(h_k)  (UNSCALED) -------
__global__ __launch_bounds__(256) void k_grads(int t) {
    __shared__ float As[32][33], Bs[32][33];
    int j0 = blockIdx.x * 32, i0 = blockIdx.y * 32;
    int tx = threadIdx.x & 15, ty = threadIdx.x >> 4;
    const float* A = (blockIdx.z == 0) ? g_dpre : g_diff;
    float a00 = 0.f, a01 = 0.f, a10 = 0.f, a11 = 0.f;
    for (int k0 = 0; k0 < BB; k0 += 32) {
        for (int i = threadIdx.x; i < 1024; i += 256) {
            int r = i >> 5, c = i & 31;
            As[r][c] = A[(size_t)(k0 + r)*DD + i0 + c];
            if (blockIdx.z == 0)
                Bs[r][c] = g_K[(size_t)t*NBD + (size_t)(k0 + r)*DD + j0 + c];
            else
                Bs[r][c] = fmaxf(g_h[(size_t)(64 + k0 + r)*DD + j0 + c], 0.f);
        }
        __syncthreads();
        #pragma unroll
        for (int k = 0; k < 32; k++) {
            float x0 = As[k][ty*2], x1 = As[k][ty*2+1];
            float y0 = Bs[k][tx*2], y1 = Bs[k][tx*2+1];
            a00 += x0*y0; a01 += x0*y1; a10 += x1*y0; a11 += x1*y1;
        }
        __syncthreads();
    }
    int i = i0 + ty*2, j = j0 + tx*2;
    float* G = (blockIdx.z == 0) ? g_gW1 : g_gW2;
    G[(size_t)i*DD + j] = a00;       G[(size_t)i*DD + j + 1] = a01;
    G[(size_t)(i+1)*DD + j] = a10;   G[(size_t)(i+1)*DD + j + 1] = a11;
}

// ---------------- per-step: momentum + weight-decay update (scale applied here) -----------
__global__ void k_update(int t) {
    float th = g_th[t], et = g_et[t], al = g_al[t];
    float ls = g_loss[t] * (1.f / (float)NBD);
    float pt = (ls >= 1e-10f && ls <= 1e10f) ? 1.f : 0.f;
    float s = th * pt * (2.f / (float)NBD);
    float oa = 1.f - al;
    int bid = blockIdx.x;
    if (bid < 1024) {
        int i = bid * 256 + threadIdx.x;
        float m = et * g_M1w[i] - s * g_gW1[i];
        g_M1w[i] = m; g_W1[i] = oa * g_W1[i] + m;
    } else if (bid < 2048) {
        int i = (bid - 1024) * 256 + threadIdx.x;
        float m = et * g_M2w[i] - s * g_gW2[i];
        g_M2w[i] = m; g_W2[i] = oa * g_W2[i] + m;
    } else {
        int i = (bid - 2048) * 256 + threadIdx.x;  // 0..1023
        if (i < 512) {
            float g = 0.f;
            for (int b = 0; b < BB; b++) g += g_dpre[(size_t)b*DD + i];
            float m = et * g_M1b[i] - s * g;
            g_M1b[i] = m; g_b1[i] = oa * g_b1[i] + m;
        } else if (i < 1024) {
            int j = i - 512;
            float g = 0.f;
            for (int b = 0; b < BB; b++) g += g_diff[(size_t)b*DD + j];
            float m = et * g_M2b[j] - s * g;
            g_M2b[j] = m; g_b2[j] = oa * g_b2[j] + m;
        }
    }
}

// ---------------- launch ----------------
extern "C" void kernel_launch(void* const* d_in, const int* in_sizes, int n_in,
                              void* d_out, int out_size) {
    const float* x   = (const float*)d_in[0];
    const float* WQ  = (const float*)d_in[1];
    const float* WK  = (const float*)d_in[2];
    const float* WV  = (const float*)d_in[3];
    const float* thw = (const float*)d_in[4];
    const float* thb = (const float*)d_in[5];
    const float* etw = (const float*)d_in[6];
    const float* etb = (const float*)d_in[7];
    const float* alw = (const float*)d_in[8];
    const float* alb = (const float*)d_in[9];
    const float* W1  = (const float*)d_in[10];
    const float* b1  = (const float*)d_in[11];
    const float* W2  = (const float*)d_in[12];
    const float* b2  = (const float*)d_in[13];
    float* out = (float*)d_out;
    int dup = (out_size >= 2 * BTD) ? 1 : 0;

    k_init<<<1024, 256>>>(W1, b1, W2, b2);
    k_gates<<<TT, 256>>>(x, thw, thb, etw, etb, alw, alb);
    k_qkv<<<dim3(16, 256, 3), 256>>>(x, WQ, WK, WV);
    for (int t = 0; t < TT; t++) {
        k_h<<<dim3(16, 4), 256>>>(t);
        k_out<<<dim3(16, 4), 256>>>(t, out, dup);
        k_dpre<<<dim3(16, 2), 256>>>(t);
        k_grads<<<dim3(16, 16, 2), 256>>>(t);
        k_update<<<2052, 256>>>(t);
    }
}

// round 4
// speedup vs baseline: 2.0449x; 2.0449x over previous
#include <cuda_runtime.h>
#include <math.h>

#define BB 64
#define TT 128
#define DD 512
#define NBD (BB*DD)        /* 32768 */
#define BTD (BB*TT*DD)     /* 4194304 */
#define G_CTAS 128

typedef unsigned long long u64;

// ---------------- device state ----------------
__device__ float g_Q[TT*NBD];
__device__ float g_K[TT*NBD];
__device__ float g_V[TT*NBD];
__device__ float g_th[TT], g_et[TT], g_al[TT];
__device__ float g_W1[DD*DD], g_M1w[DD*DD], g_b1[DD], g_M1b[DD];
__device__ float g_W2[DD*DD], g_M2w[DD*DD], g_b2[DD], g_M2b[DD];
__device__ float g_h[2*NBD];      // raw pre-activations: rows 0-63 q-path, 64-127 k-path
__device__ float g_diff[NBD];     // out - v (UNSCALED)
__device__ float g_dpre[NBD];     // masked diff@W2 (UNSCALED)
__device__ float g_gW1[DD*DD], g_gW2[DD*DD];
__device__ float g_loss[TT];
__device__ unsigned g_barcnt;
__device__ volatile unsigned g_bargen;

// ---------------- f32x2 helpers ----------------
__device__ __forceinline__ u64 pk2(float x, float y){
    u64 r; asm("mov.b64 %0, {%1, %2};" : "=l"(r) : "f"(x), "f"(y)); return r;
}
__device__ __forceinline__ void fma2(u64 &c, u64 a, u64 b){
    asm("fma.rn.f32x2 %0, %1, %2, %0;" : "+l"(c) : "l"(a), "l"(b));
}
__device__ __forceinline__ float2 up2(u64 v){
    float lo, hi; asm("mov.b64 {%0, %1}, %2;" : "=f"(lo), "=f"(hi) : "l"(v));
    return make_float2(lo, hi);
}

// ---------------- grid barrier (monotonic count; reset per launch in k_init) --------------
__device__ __forceinline__ void gbar(unsigned &gen){
    __syncthreads();
    if (threadIdx.x == 0){
        __threadfence();                         // order my writes; CCTL.IVALL
        unsigned target = (gen + 1u) * (unsigned)G_CTAS;
        unsigned arrived = atomicAdd(&g_barcnt, 1u) + 1u;
        if (arrived == target){
            g_bargen = gen + 1u;
        } else {
            while (g_bargen < gen + 1u) { __nanosleep(64); }
        }
        __threadfence();                         // invalidate L1 before reading peers' data
    }
    __syncthreads();
    gen++;
}

// ---------------- init: copy weights, zero momentum + loss + barrier ----------------
__global__ void k_init(const float* __restrict__ W1, const float* __restrict__ b1,
                       const float* __restrict__ W2, const float* __restrict__ b2) {
    int i = blockIdx.x * 256 + threadIdx.x;
    if (i < DD*DD) { g_W1[i] = W1[i]; g_M1w[i] = 0.f; g_W2[i] = W2[i]; g_M2w[i] = 0.f; }
    if (i < DD)    { g_b1[i] = b1[i]; g_M1b[i] = 0.f; g_b2[i] = b2[i]; g_M2b[i] = 0.f; }
    if (i < TT)    g_loss[i] = 0.f;
    if (i == 0)    { g_barcnt = 0u; g_bargen = 0u; }
}

// ---------------- gates ----------------
__global__ void k_gates(const float* __restrict__ x,
                        const float* __restrict__ thw, const float* __restrict__ thb,
                        const float* __restrict__ etw, const float* __restrict__ etb,
                        const float* __restrict__ alw, const float* __restrict__ alb) {
    int t = blockIdx.x, tid = threadIdx.x, lane = tid & 31, warp = tid >> 5;
    __shared__ float red[8];
    for (int g = 0; g < 3; g++) {
        const float* w = (g == 0) ? thw : ((g == 1) ? etw : alw);
        float b0 = (g == 0) ? thb[0] : ((g == 1) ? etb[0] : alb[0]);
        float acc = 0.f;
        for (int bi = warp; bi < BB; bi += 8) {
            const float* xr = x + ((size_t)bi * TT + t) * DD;
            float s = 0.f;
            for (int k = lane; k < DD; k += 32) s += xr[k] * w[k];
            #pragma unroll
            for (int o = 16; o; o >>= 1) s += __shfl_down_sync(0xffffffffu, s, o);
            if (lane == 0) acc += 1.f / (1.f + expf(-(s + b0)));
        }
        if (lane == 0) red[warp] = acc;
        __syncthreads();
        if (tid == 0) {
            float s = 0.f;
            #pragma unroll
            for (int i = 0; i < 8; i++) s += red[i];
            s *= (1.f / (float)BB);
            if (g == 0) g_th[t] = s; else if (g == 1) g_et[t] = s; else g_al[t] = s;
        }
        __syncthreads();
    }
}

// ---------------- QKV: O[m][n] = sum_k x_row(m)[k] * W[n][k], m = t*64+b ----------------
__global__ __launch_bounds__(256) void k_qkv(const float* __restrict__ x,
                       const float* __restrict__ WQ, const float* __restrict__ WK,
                       const float* __restrict__ WV) {
    __shared__ float As[64][33], Bsh[64][33];
    int n0 = blockIdx.x * 64, m0 = blockIdx.y * 64;
    const float* W = (blockIdx.z == 0) ? WQ : ((blockIdx.z == 1) ? WK : WV);
    float* O = (blockIdx.z == 0) ? g_Q : ((blockIdx.z == 1) ? g_K : g_V);
    int tid = threadIdx.x;
    int r0 = (tid >> 4) * 4, c0 = (tid & 15) * 4;
    float acc[4][4];
    #pragma unroll
    for (int i = 0; i < 4; i++)
        #pragma unroll
        for (int j = 0; j < 4; j++) acc[i][j] = 0.f;
    for (int kb = 0; kb < 16; kb++) {
        #pragma unroll
        for (int i = 0; i < 2; i++) {
            int e = tid + i*256;          // 0..511 float4 slots
            int row = e >> 3, kq = e & 7;
            int m = m0 + row;
            float4 xv = *(const float4*)&x[((size_t)(m & 63)*TT + (m >> 6))*DD + kb*32 + kq*4];
            As[row][4*kq+0]=xv.x; As[row][4*kq+1]=xv.y; As[row][4*kq+2]=xv.z; As[row][4*kq+3]=xv.w;
            float4 wv = *(const float4*)&W[(size_t)(n0 + row)*DD + kb*32 + kq*4];
            Bsh[row][4*kq+0]=wv.x; Bsh[row][4*kq+1]=wv.y; Bsh[row][4*kq+2]=wv.z; Bsh[row][4*kq+3]=wv.w;
        }
        __syncthreads();
        #pragma unroll 4
        for (int kk = 0; kk < 32; kk++) {
            float a0 = As[r0+0][kk], a1 = As[r0+1][kk], a2 = As[r0+2][kk], a3 = As[r0+3][kk];
            float b0 = Bsh[c0+0][kk], b1 = Bsh[c0+1][kk], b2 = Bsh[c0+2][kk], b3 = Bsh[c0+3][kk];
            acc[0][0]+=a0*b0; acc[0][1]+=a0*b1; acc[0][2]+=a0*b2; acc[0][3]+=a0*b3;
            acc[1][0]+=a1*b0; acc[1][1]+=a1*b1; acc[1][2]+=a1*b2; acc[1][3]+=a1*b3;
            acc[2][0]+=a2*b0; acc[2][1]+=a2*b1; acc[2][2]+=a2*b2; acc[2][3]+=a2*b3;
            acc[3][0]+=a3*b0; acc[3][1]+=a3*b1; acc[3][2]+=a3*b2; acc[3][3]+=a3*b3;
        }
        __syncthreads();
    }
    #pragma unroll
    for (int i = 0; i < 4; i++) {
        float4 v = make_float4(acc[i][0], acc[i][1], acc[i][2], acc[i][3]);
        *(float4*)&O[(size_t)(m0 + r0 + i)*DD + n0 + c0] = v;
    }
}

// ======================= persistent scan kernel =======================
#define SMBYTES 26368
__global__ __launch_bounds__(256, 1) void k_scan(float* __restrict__ out, int dup) {
    __shared__ __align__(16) unsigned char smraw[SMBYTES];
    __shared__ float red[8];
    float (*As)[512]  = (float(*)[512])smraw;                     // 16384 B
    float (*Bs)[66]   = (float(*)[66])(smraw + 8*512*4);          // +8448 B
    float (*Ag)[33]   = (float(*)[33])smraw;                      // 8448 B
    float (*Bg)[68]   = (float(*)[68])(smraw + 64*33*4);          // +17408 B

    int cta = blockIdx.x, tid = threadIdx.x;
    unsigned gen = 0;

    // ---- local lambdas as device code (written inline per phase) ----
    for (int t = 0; t < TT; t++) {
        // ======== phase U: apply update from step t-1 ========
        if (t > 0) {
            float th = g_th[t-1], et = g_et[t-1], al = g_al[t-1];
            float ls = g_loss[t-1] * (1.f/(float)NBD);
            float pt = (ls >= 1e-10f && ls <= 1e10f) ? 1.f : 0.f;
            float s  = th * pt * (2.f/(float)NBD);
            float oa = 1.f - al;
            size_t base = (size_t)cta * 2048;
            #pragma unroll
            for (int i = 0; i < 2; i++) {
                size_t idx = base + (size_t)tid*4 + (size_t)i*1024;
                float4 g1 = *(const float4*)&g_gW1[idx];
                float4 m1 = *(const float4*)&g_M1w[idx];
                float4 w1 = *(const float4*)&g_W1[idx];
                m1.x = et*m1.x - s*g1.x; w1.x = oa*w1.x + m1.x;
                m1.y = et*m1.y - s*g1.y; w1.y = oa*w1.y + m1.y;
                m1.z = et*m1.z - s*g1.z; w1.z = oa*w1.z + m1.z;
                m1.w = et*m1.w - s*g1.w; w1.w = oa*w1.w + m1.w;
                *(float4*)&g_M1w[idx] = m1; *(float4*)&g_W1[idx] = w1;
                float4 g2 = *(const float4*)&g_gW2[idx];
                float4 m2 = *(const float4*)&g_M2w[idx];
                float4 w2 = *(const float4*)&g_W2[idx];
                m2.x = et*m2.x - s*g2.x; w2.x = oa*w2.x + m2.x;
                m2.y = et*m2.y - s*g2.y; w2.y = oa*w2.y + m2.y;
                m2.z = et*m2.z - s*g2.z; w2.z = oa*w2.z + m2.z;
                m2.w = et*m2.w - s*g2.w; w2.w = oa*w2.w + m2.w;
                *(float4*)&g_M2w[idx] = m2; *(float4*)&g_W2[idx] = w2;
            }
            if (cta < 8 && tid < 128) {
                int col = (cta & 3) * 128 + tid;
                const float* src = (cta < 4) ? g_dpre : g_diff;
                float g = 0.f;
                #pragma unroll 8
                for (int b = 0; b < BB; b++) g += src[(size_t)b*DD + col];
                if (cta < 4) { float m = et*g_M1b[col] - s*g; g_M1b[col] = m; g_b1[col] = oa*g_b1[col] + m; }
                else         { float m = et*g_M2b[col] - s*g; g_M2b[col] = m; g_b2[col] = oa*g_b2[col] + m; }
            }
            gbar(gen);
        }

        // ======== phases H (mode 0) and O (mode 1): 8x64 tiles, 128 CTAs ========
        for (int mode = 0; mode < 2; mode++) {
            int m0 = (cta >> 3) * 8, n0 = (cta & 7) * 64;
            // load A tile: 8 rows x 512 k (full K)
            #pragma unroll
            for (int i = 0; i < 4; i++) {
                int e = tid + i*256;             // 0..1023 float4 slots
                int row = e >> 7, k4 = e & 127;
                int m = m0 + row;
                const float* src;
                if (mode == 0)
                    src = (m < 64) ? (g_Q + (size_t)t*NBD + (size_t)m*DD)
                                   : (g_K + (size_t)t*NBD + (size_t)(m-64)*DD);
                else
                    src = g_h + (size_t)m*DD;
                float4 v = *(const float4*)(src + k4*4);
                if (mode == 1) { v.x=fmaxf(v.x,0.f); v.y=fmaxf(v.y,0.f); v.z=fmaxf(v.z,0.f); v.w=fmaxf(v.w,0.f); }
                *(float4*)&As[row][k4*4] = v;
            }
            const float* W = (mode == 0) ? g_W1 : g_W2;
            int r = tid >> 5, c = tid & 31;
            u64 acc0 = 0ull, acc1 = 0ull;
            for (int kb = 0; kb < 16; kb++) {
                #pragma unroll
                for (int i = 0; i < 2; i++) {
                    int e = tid + i*256;         // 0..511 float4 slots
                    int n = e >> 3, kq = e & 7;
                    float4 w = *(const float4*)&W[(size_t)(n0 + n)*DD + kb*32 + kq*4];
                    Bs[4*kq+0][n]=w.x; Bs[4*kq+1][n]=w.y; Bs[4*kq+2][n]=w.z; Bs[4*kq+3][n]=w.w;
                }
                __syncthreads();
                const float* ar = &As[r][kb*32];
                #pragma unroll
                for (int kk = 0; kk < 32; kk += 2) {
                    float a0 = ar[kk], a1 = ar[kk+1];
                    u64 b0 = *(const u64*)&Bs[kk][2*c];
                    u64 b1 = *(const u64*)&Bs[kk+1][2*c];
                    fma2(acc0, pk2(a0,a0), b0);
                    fma2(acc1, pk2(a1,a1), b1);
                }
                __syncthreads();
            }
            float2 s0 = up2(acc0), s1 = up2(acc1);
            float r0v = s0.x + s1.x, r1v = s0.y + s1.y;
            int m = m0 + r, n = n0 + 2*c;
            if (mode == 0) {
                r0v += g_b1[n]; r1v += g_b1[n+1];
                *(float2*)&g_h[(size_t)m*DD + n] = make_float2(r0v, r1v);
            } else {
                r0v += g_b2[n]; r1v += g_b2[n+1];
                if (m < 64) {
                    size_t o = ((size_t)m*TT + t)*DD + n;
                    *(float2*)&out[o] = make_float2(r0v, r1v);
                    if (dup) *(float2*)&out[BTD + o] = make_float2(r0v, r1v);
                } else {
                    int b = m - 64;
                    float2 v = *(const float2*)&g_V[(size_t)t*NBD + (size_t)b*DD + n];
                    float d0 = r0v - v.x, d1 = r1v - v.y;
                    *(float2*)&g_diff[(size_t)b*DD + n] = make_float2(d0, d1);
                    float ls = d0*d0 + d1*d1;
                    #pragma unroll
                    for (int o2 = 16; o2; o2 >>= 1) ls += __shfl_down_sync(0xffffffffu, ls, o2);
                    if ((tid & 31) == 0) red[tid >> 5] = ls;
                    __syncthreads();
                    if (tid == 0) {
                        float s = 0.f;
                        #pragma unroll
                        for (int i = 0; i < 8; i++) s += red[i];
                        atomicAdd(&g_loss[t], s);
                    }
                }
            }
            gbar(gen);
            if (mode == 1 && t == TT-1) break;   // nothing after final O
        }
        if (t == TT-1) break;

        // ======== phase D: CTAs 0-63 -> dpre ; CTAs 64-127 -> gW2 ========
        if (cta < 64) {
            int m0 = (cta >> 3) * 8, n0 = (cta & 7) * 64;
            #pragma unroll
            for (int i = 0; i < 4; i++) {
                int e = tid + i*256;
                int row = e >> 7, k4 = e & 127;
                float4 v = *(const float4*)&g_diff[(size_t)(m0 + row)*DD + k4*4];
                *(float4*)&As[row][k4*4] = v;
            }
            int r = tid >> 5, c = tid & 31;
            u64 acc0 = 0ull, acc1 = 0ull;
            for (int kb = 0; kb < 16; kb++) {
                #pragma unroll
                for (int i = 0; i < 2; i++) {
                    int e = tid + i*256;
                    int kk = e >> 4, nq = e & 15;
                    float4 w = *(const float4*)&g_W2[(size_t)(kb*32 + kk)*DD + n0 + nq*4];
                    *(float2*)&Bs[kk][4*nq]   = make_float2(w.x, w.y);
                    *(float2*)&Bs[kk][4*nq+2] = make_float2(w.z, w.w);
                }
                __syncthreads();
                const float* ar = &As[r][kb*32];
                #pragma unroll
                for (int kk = 0; kk < 32; kk += 2) {
                    float a0 = ar[kk], a1 = ar[kk+1];
                    u64 b0 = *(const u64*)&Bs[kk][2*c];
                    u64 b1 = *(const u64*)&Bs[kk+1][2*c];
                    fma2(acc0, pk2(a0,a0), b0);
                    fma2(acc1, pk2(a1,a1), b1);
                }
                __syncthreads();
            }
            float2 s0 = up2(acc0), s1 = up2(acc1);
            float r0v = s0.x + s1.x, r1v = s0.y + s1.y;
            int m = m0 + r, n = n0 + 2*c;
            float2 hp = *(const float2*)&g_h[(size_t)(64 + m)*DD + n];
            float2 o;
            o.x = (hp.x > 0.f) ? r0v : 0.f;
            o.y = (hp.y > 0.f) ? r1v : 0.f;
            *(float2*)&g_dpre[(size_t)m*DD + n] = o;
        } else {
            int tbase = cta - 64;
            #pragma unroll
            for (int pass = 0; pass < 2; pass++) {
                int id = tbase + pass*64;
                int i0 = (id >> 3) * 32, j0 = (id & 7) * 64;
                #pragma unroll
                for (int i = 0; i < 8; i++) {
                    int e = tid + i*256; int b = e >> 5, ii = e & 31;
                    Ag[b][ii] = g_diff[(size_t)b*DD + i0 + ii];
                }
                #pragma unroll
                for (int i = 0; i < 4; i++) {
                    int e = tid + i*256; int b = e >> 4, jq = e & 15;
                    float4 v = *(const float4*)&g_h[(size_t)(64 + b)*DD + j0 + jq*4];
                    v.x=fmaxf(v.x,0.f); v.y=fmaxf(v.y,0.f); v.z=fmaxf(v.z,0.f); v.w=fmaxf(v.w,0.f);
                    *(float4*)&Bg[b][jq*4] = v;
                }
                __syncthreads();
                int ty = tid >> 4, tx = tid & 15;
                float acc[2][4];
                #pragma unroll
                for (int i=0;i<2;i++)
                    #pragma unroll
                    for (int j=0;j<4;j++) acc[i][j]=0.f;
                #pragma unroll 4
                for (int b = 0; b < 64; b++) {
                    float a0 = Ag[b][2*ty], a1 = Ag[b][2*ty+1];
                    float4 bv = *(const float4*)&Bg[b][4*tx];
                    acc[0][0]+=a0*bv.x; acc[0][1]+=a0*bv.y; acc[0][2]+=a0*bv.z; acc[0][3]+=a0*bv.w;
                    acc[1][0]+=a1*bv.x; acc[1][1]+=a1*bv.y; acc[1][2]+=a1*bv.z; acc[1][3]+=a1*bv.w;
                }
                __syncthreads();
                int i = i0 + 2*ty, j = j0 + 4*tx;
                *(float4*)&g_gW2[(size_t)i*DD + j]     = make_float4(acc[0][0],acc[0][1],acc[0][2],acc[0][3]);
                *(float4*)&g_gW2[(size_t)(i+1)*DD + j] = make_float4(acc[1][0],acc[1][1],acc[1][2],acc[1][3]);
            }
        }
        gbar(gen);

        // ======== phase G: gW1 = dpre^T @ k, 128 tiles ========
        {
            int i0 = (cta >> 3) * 32, j0 = (cta & 7) * 64;
            const float* Bsrc = g_K + (size_t)t*NBD;
            #pragma unroll
            for (int i = 0; i < 8; i++) {
                int e = tid + i*256; int b = e >> 5, ii = e & 31;
                Ag[b][ii] = g_dpre[(size_t)b*DD + i0 + ii];
            }
            #pragma unroll
            for (int i = 0; i < 4; i++) {
                int e = tid + i*256; int b = e >> 4, jq = e & 15;
                float4 v = *(const float4*)&Bsrc[(size_t)b*DD + j0 + jq*4];
                *(float4*)&Bg[b][jq*4] = v;
            }
            __syncthreads();
            int ty = tid >> 4, tx = tid & 15;
            float acc[2][4];
            #pragma unroll
            for (int i=0;i<2;i++)
                #pragma unroll
                for (int j=0;j<4;j++) acc[i][j]=0.f;
            #pragma unroll 4
            for (int b = 0; b < 64; b++) {
                float a0 = Ag[b][2*ty], a1 = Ag[b][2*ty+1];
                float4 bv = *(const float4*)&Bg[b][4*tx];
                acc[0][0]+=a0*bv.x; acc[0][1]+=a0*bv.y; acc[0][2]+=a0*bv.z; acc[0][3]+=a0*bv.w;
                acc[1][0]+=a1*bv.x; acc[1][1]+=a1*bv.y; acc[1][2]+=a1*bv.z; acc[1][3]+=a1*bv.w;
            }
            __syncthreads();
            int i = i0 + 2*ty, j = j0 + 4*tx;
            *(float4*)&g_gW1[(size_t)i*DD + j]     = make_float4(acc[0][0],acc[0][1],acc[0][2],acc[0][3]);
            *(float4*)&g_gW1[(size_t)(i+1)*DD + j] = make_float4(acc[1][0],acc[1][1],acc[1][2],acc[1][3]);
        }
        gbar(gen);
    }
}

// ---------------- launch ----------------
extern "C" void kernel_launch(void* const* d_in, const int* in_sizes, int n_in,
                              void* d_out, int out_size) {
    const float* x   = (const float*)d_in[0];
    const float* WQ  = (const float*)d_in[1];
    const float* WK  = (const float*)d_in[2];
    const float* WV  = (const float*)d_in[3];
    const float* thw = (const float*)d_in[4];
    const float* thb = (const float*)d_in[5];
    const float* etw = (const float*)d_in[6];
    const float* etb = (const float*)d_in[7];
    const float* alw = (const float*)d_in[8];
    const float* alb = (const float*)d_in[9];
    const float* W1  = (const float*)d_in[10];
    const float* b1  = (const float*)d_in[11];
    const float* W2  = (const float*)d_in[12];
    const float* b2  = (const float*)d_in[13];
    float* out = (float*)d_out;
    int dup = (out_size >= 2 * BTD) ? 1 : 0;

    k_init<<<1024, 256>>>(W1, b1, W2, b2);
    k_gates<<<TT, 256>>>(x, thw, thb, etw, etb, alw, alb);
    k_qkv<<<dim3(8, 128, 3), 256>>>(x, WQ, WK, WV);
    k_scan<<<G_CTAS, 256>>>(out, dup);
}